// round 11
// baseline (speedup 1.0000x reference)
#include <cuda_runtime.h>

#define TBLOCK  128
#define NWARP   4
#define NFILT   11
#define NCOLS   262144
#define NROWS   128
#define WTILE   128                 // outputs per warp

typedef unsigned long long u64;

__device__ __forceinline__ u64 pack2(float lo, float hi) {
    u64 r; asm("mov.b64 %0, {%1, %2};" : "=l"(r) : "f"(lo), "f"(hi)); return r;
}
__device__ __forceinline__ void unpack2(u64 v, float& lo, float& hi) {
    asm("mov.b64 {%0, %1}, %2;" : "=f"(lo), "=f"(hi) : "l"(v));
}
__device__ __forceinline__ u64 fma2(u64 a, u64 b, u64 c) {
    u64 d; asm("fma.rn.f32x2 %0, %1, %2, %3;" : "=l"(d) : "l"(a), "l"(b), "l"(c)); return d;
}
// Load complex column c with SAME zero padding (boundary lanes only).
__device__ __forceinline__ u64 ldc_z(const float2* xrow, int c) {
    if (c >= 0 && c < NCOLS) {
        float2 v = __ldg(xrow + c);
        return pack2(v.x, v.y);
    }
    return 0ull;
}

__global__ void __launch_bounds__(TBLOCK, 8) fir_shfl_kernel(
    const float2* __restrict__ X, const float* __restrict__ phi,
    float2* __restrict__ Y)
{
    const int lane = threadIdx.x & 31;
    const int wid  = threadIdx.x >> 5;
    const int row  = blockIdx.y;
    const int W0   = (blockIdx.x * NWARP + wid) * WTILE;   // warp's first output col
    const int c0   = W0 + 4 * lane;                        // this thread's first col

    const float2* __restrict__ xrow = X + (size_t)row * NCOLS;
    float2* __restrict__ yrow       = Y + (size_t)row * NCOLS;

    // Own 4 complexes as u64 (a float2 complex IS the u64 bit pattern).
    ulonglong2 p0 = __ldg((const ulonglong2*)(xrow + c0));
    ulonglong2 p1 = __ldg((const ulonglong2*)(xrow + c0 + 2));
    u64 v0 = p0.x, v1 = p0.y, v2 = p1.x, v3 = p1.y;

    // Coefficients A[k] = (wr_k, wi_k) — phi's native layout.
    u64 A[NFILT];
#pragma unroll
    for (int k = 0; k < NFILT; k++) {
        float2 w = __ldg(((const float2*)phi) + k);
        A[k] = pack2(w.x, w.y);
    }

    // Halo via shuffle. Window w[j] = complex at col c0 - 5 + j, j = 0..13.
    //   w[0]    = lane-2's v3      w[1..4] = lane-1's v0..v3
    //   w[5..8] = own v0..v3
    //   w[9..12]= lane+1's v0..v3  w[13]   = lane+2's v0
    const unsigned FULL = 0xffffffffu;
    u64 hv0 = __shfl_up_sync(FULL, v3, 2);
    u64 hv1 = __shfl_up_sync(FULL, v0, 1);
    u64 hv2 = __shfl_up_sync(FULL, v1, 1);
    u64 hv3 = __shfl_up_sync(FULL, v2, 1);
    u64 hv4 = __shfl_up_sync(FULL, v3, 1);
    u64 hw0 = __shfl_down_sync(FULL, v0, 1);
    u64 hw1 = __shfl_down_sync(FULL, v1, 1);
    u64 hw2 = __shfl_down_sync(FULL, v2, 1);
    u64 hw3 = __shfl_down_sync(FULL, v3, 1);
    u64 hw4 = __shfl_down_sync(FULL, v0, 2);

    // Warp-boundary lanes patch halo with direct (zero-padded) loads.
    if (lane == 0) {
        hv0 = ldc_z(xrow, c0 - 5);
        hv1 = ldc_z(xrow, c0 - 4);
        hv2 = ldc_z(xrow, c0 - 3);
        hv3 = ldc_z(xrow, c0 - 2);
        hv4 = ldc_z(xrow, c0 - 1);
    } else if (lane == 1) {
        hv0 = ldc_z(xrow, c0 - 5);
    }
    if (lane == 31) {
        hw0 = ldc_z(xrow, c0 + 4);
        hw1 = ldc_z(xrow, c0 + 5);
        hw2 = ldc_z(xrow, c0 + 6);
        hw3 = ldc_z(xrow, c0 + 7);
        hw4 = ldc_z(xrow, c0 + 8);
    } else if (lane == 30) {
        hw4 = ldc_z(xrow, c0 + 8);
    }

    u64 w[14] = {hv0, hv1, hv2, hv3, hv4, v0, v1, v2, v3, hw0, hw1, hw2, hw3, hw4};

    // Output i (col c0+i), tap k: col c0+i+k-5 = w[i+k].
    // P[i] = sum_k xr*(wr,wi);  Q[i] = sum_k xi*(wr,wi)
    u64 P[4], Q[4];
#pragma unroll
    for (int i = 0; i < 4; i++) { P[i] = 0ull; Q[i] = 0ull; }

#pragma unroll
    for (int j = 0; j < 14; j++) {
        float xr, xi;
        unpack2(w[j], xr, xi);
        u64 xrr = pack2(xr, xr);
        u64 xii = pack2(xi, xi);
#pragma unroll
        for (int i = 0; i < 4; i++) {
            const int k = j - i;                // compile-time after unroll
            if (k >= 0 && k < NFILT) {
                P[i] = fma2(xrr, A[k], P[i]);
                Q[i] = fma2(xii, A[k], Q[i]);
            }
        }
    }

    // out = (P.lo - Q.hi, P.hi + Q.lo)
    float4 o0, o1;
    float prr, pri, qir, qii;
    unpack2(P[0], prr, pri); unpack2(Q[0], qir, qii); o0.x = prr - qii; o0.y = pri + qir;
    unpack2(P[1], prr, pri); unpack2(Q[1], qir, qii); o0.z = prr - qii; o0.w = pri + qir;
    unpack2(P[2], prr, pri); unpack2(Q[2], qir, qii); o1.x = prr - qii; o1.y = pri + qir;
    unpack2(P[3], prr, pri); unpack2(Q[3], qir, qii); o1.z = prr - qii; o1.w = pri + qir;

    float4* yo = (float4*)(yrow + c0);
    yo[0] = o0;
    yo[1] = o1;
}

extern "C" void kernel_launch(void* const* d_in, const int* in_sizes, int n_in,
                              void* d_out, int out_size)
{
    const float2* X   = (const float2*)d_in[0];
    const float*  phi = (const float*)d_in[1];
    float2*       Y   = (float2*)d_out;

    dim3 grid(NCOLS / (WTILE * NWARP), NROWS);   // (512, 128)
    fir_shfl_kernel<<<grid, TBLOCK>>>(X, phi, Y);
}

// round 12
// speedup vs baseline: 1.3180x; 1.3180x over previous
#include <cuda_runtime.h>
#include <cstdint>

#define TBLOCK  128
#define NWARP   4
#define NFILT   11
#define NCOLS   262144
#define NROWS   128
#define WTILE   128                 // outputs per warp-tile
#define TPW     4                   // tiles per warp (pipelined chain)
#define STAGES  3
#define CHUNKS  72                  // float4 chunks per tile: complexes [T0-6, T0+138)
#define NF4ROW  (NCOLS / 2)

typedef unsigned long long u64;

__device__ __forceinline__ u64 pack2(float lo, float hi) {
    u64 r; asm("mov.b64 %0, {%1, %2};" : "=l"(r) : "f"(lo), "f"(hi)); return r;
}
__device__ __forceinline__ void unpack2(u64 v, float& lo, float& hi) {
    asm("mov.b64 {%0, %1}, %2;" : "=f"(lo), "=f"(hi) : "l"(v));
}
__device__ __forceinline__ u64 fma2(u64 a, u64 b, u64 c) {
    u64 d; asm("fma.rn.f32x2 %0, %1, %2, %3;" : "=l"(d) : "l"(a), "l"(b), "l"(c)); return d;
}
__device__ __forceinline__ void cpa16(uint32_t s, const float4* g) {
    asm volatile("cp.async.cg.shared.global [%0], [%1], 16;" :: "r"(s), "l"(g));
}
__device__ __forceinline__ void cpa_commit() {
    asm volatile("cp.async.commit_group;");
}
template <int N> __device__ __forceinline__ void cpa_wait() {
    asm volatile("cp.async.wait_group %0;" :: "n"(N));
}
// Swizzle chunk index so stride-2 reads (d = 2*lane + q) are bank-conflict-free.
__device__ __forceinline__ int swz(int d) { return d ^ ((d >> 3) & 1); }

__global__ void __launch_bounds__(TBLOCK, 10) fir_cpwarp_kernel(
    const float2* __restrict__ X, const float* __restrict__ phi,
    float2* __restrict__ Y)
{
    // Per-warp private 3-stage AoS ring. sbuf[w][s][swz(d)] holds gmem chunk g0+d.
    __shared__ __align__(16) float4 sbuf[NWARP][STAGES][CHUNKS];

    const int lane = threadIdx.x & 31;
    const int wid  = threadIdx.x >> 5;
    const int row  = blockIdx.y;
    const float4* x4 = (const float4*)(X + (size_t)row * NCOLS);
    float2* yrow     = Y + (size_t)row * NCOLS;

    // Coefficients A[k] = (wr_k, wi_k) — phi's native layout.
    u64 A[NFILT];
#pragma unroll
    for (int k = 0; k < NFILT; k++) {
        float2 w = __ldg(((const float2*)phi) + k);
        A[k] = pack2(w.x, w.y);
    }

    // Warp's chain: tiles [wt0, wt0+TPW), tile t covers cols [(wt0+t)*128, +128).
    const int wt0 = (blockIdx.x * NWARP + wid) * TPW;

    // Issue staging of tile t into stage (t % 3). Chunk d (0..71) = gmem float4
    // g0 + d, g0 = T0/2 - 3 (window origin col T0-6). Invalid chunks -> STS zero.
    #define ISSUE_TILE(t) do {                                                     \
        const int g0  = (wt0 + (t)) * 64 - 3;                                      \
        float4* dst = &sbuf[wid][(t) % STAGES][0];                                 \
        {   const int d = lane;      const int u = g0 + d;                         \
            uint32_t a = (uint32_t)__cvta_generic_to_shared(&dst[swz(d)]);         \
            if (u >= 0 && u < NF4ROW) cpa16(a, x4 + u);                            \
            else dst[swz(d)] = make_float4(0.f, 0.f, 0.f, 0.f);                    \
        }                                                                          \
        {   const int d = lane + 32; const int u = g0 + d;                         \
            uint32_t a = (uint32_t)__cvta_generic_to_shared(&dst[swz(d)]);         \
            if (u >= 0 && u < NF4ROW) cpa16(a, x4 + u);                            \
            else dst[swz(d)] = make_float4(0.f, 0.f, 0.f, 0.f);                    \
        }                                                                          \
        if (lane < 8) {                                                            \
            const int d = lane + 64; const int u = g0 + d;                         \
            uint32_t a = (uint32_t)__cvta_generic_to_shared(&dst[swz(d)]);         \
            if (u >= 0 && u < NF4ROW) cpa16(a, x4 + u);                            \
            else dst[swz(d)] = make_float4(0.f, 0.f, 0.f, 0.f);                    \
        }                                                                          \
        cpa_commit();                                                              \
    } while (0)

    // Prologue: two tiles in flight.
    ISSUE_TILE(0);
    ISSUE_TILE(1);

#pragma unroll
    for (int it = 0; it < TPW; ++it) {
        // Tile `it` must be complete. Newest outstanding group = tile min(it+1, TPW-1).
        if (it + 1 < TPW) cpa_wait<1>();
        else              cpa_wait<0>();
        __syncwarp();

        if (it + 2 < TPW) ISSUE_TILE(it + 2);   // stage (it+2)%3, disjoint from it,it+1

        // ---- Compute tile `it` ----
        // Thread chunks d = 2*lane + q, q=0..7 -> rel complexes [4l, 4l+15] = w[0..15].
        // Output i (col T0 + 4l + i), tap k -> w[i + k + 1].
        const float4* base = &sbuf[wid][it % STAGES][0];
        float re[16], im[16];
#pragma unroll
        for (int q = 0; q < 8; q++) {
            float4 v = base[swz(2 * lane + q)];
            re[2*q]   = v.x; im[2*q]   = v.y;
            re[2*q+1] = v.z; im[2*q+1] = v.w;
        }

        u64 P[4], Q[4];
#pragma unroll
        for (int i = 0; i < 4; i++) { P[i] = 0ull; Q[i] = 0ull; }

#pragma unroll
        for (int j = 1; j <= 14; j++) {
            u64 xrr = pack2(re[j], re[j]);
            u64 xii = pack2(im[j], im[j]);
#pragma unroll
            for (int i = 0; i < 4; i++) {
                const int k = j - 1 - i;            // compile-time after unroll
                if (k >= 0 && k < NFILT) {
                    P[i] = fma2(xrr, A[k], P[i]);
                    Q[i] = fma2(xii, A[k], Q[i]);
                }
            }
        }

        // out = (P.lo - Q.hi, P.hi + Q.lo)
        const int c0 = (wt0 + it) * WTILE + 4 * lane;
        float4 o0, o1;
        float prr, pri, qir, qii;
        unpack2(P[0], prr, pri); unpack2(Q[0], qir, qii); o0.x = prr - qii; o0.y = pri + qir;
        unpack2(P[1], prr, pri); unpack2(Q[1], qir, qii); o0.z = prr - qii; o0.w = pri + qir;
        unpack2(P[2], prr, pri); unpack2(Q[2], qir, qii); o1.x = prr - qii; o1.y = pri + qir;
        unpack2(P[3], prr, pri); unpack2(Q[3], qir, qii); o1.z = prr - qii; o1.w = pri + qir;

        float4* yo = (float4*)(yrow + c0);
        yo[0] = o0;
        yo[1] = o1;

        __syncwarp();   // all lanes done reading stage it%3 before it gets reissued
    }
    #undef ISSUE_TILE
}

extern "C" void kernel_launch(void* const* d_in, const int* in_sizes, int n_in,
                              void* d_out, int out_size)
{
    const float2* X   = (const float2*)d_in[0];
    const float*  phi = (const float*)d_in[1];
    float2*       Y   = (float2*)d_out;

    dim3 grid(NCOLS / (WTILE * NWARP * TPW), NROWS);   // (128, 128)
    fir_cpwarp_kernel<<<grid, TBLOCK>>>(X, phi, Y);
}